// round 3
// baseline (speedup 1.0000x reference)
// R3: resubmit of R2 f32x2 GEMM (R2 bench was an infra failure, not a kernel failure)
#include <cuda_runtime.h>
#include <cstdint>

#define NSTEP 16
#define NB 128
#define NE 512
#define NH 8
#define NIN 256
#define NOUT 128
#define NMEM 32769
#define NLAY 2

typedef unsigned long long ull;

__device__ __forceinline__ void fma2(ull &d, ull a, ull b) {
    asm("fma.rn.f32x2 %0, %1, %2, %0;" : "+l"(d) : "l"(a), "l"(b));
}

// ---- scratch (static device globals: allocation-free) ----
__device__ float g_X  [NSTEP * NB * NE];        // projected inputs  [t][b][e]
__device__ float g_h  [NB * NSTEP * NE];        // hidden state      [b][slot][e]
__device__ float g_qkv[NB * NSTEP * 3 * NE];    // qkv               [b][slot][3e]
__device__ float g_att[NB * NSTEP * NE];        // attention output  [b][slot][e]
__device__ float g_tmp[NB * NSTEP * NE];        // gemm epilogue tmp [b][slot][e]

// ============================================================================
// Tiled SGEMM with packed f32x2 FMA: C[m,n] = sum_k A[m,k]*W[n,k] + bias[n]
// Row m -> (b=m/L, i=m%L); A row at (b*slotA+i)*K, C row at (b*slotC+i)*N.
// BM=BN=64, BK=16, 256 threads, 4x4 microtile as 4x2 f32x2 pairs.
// A tile stored duplicated ({a,a}) so LDS yields broadcast pairs directly.
// Requires M % 64 == 0 and N % 64 == 0 (always true here).
// ============================================================================
__global__ __launch_bounds__(256) void gemm_bias_k(
    const float* __restrict__ A, const float* __restrict__ W,
    const float* __restrict__ bias, float* __restrict__ C,
    int M, int N, int K, int L, int slotA, int slotC)
{
    __shared__ float2 As[2][16][66];   // duplicated pairs, row = 528B (16B-mult)
    __shared__ float  Ws[2][16][68];

    const int tid = threadIdx.x;
    const int bm = blockIdx.y << 6;
    const int bn = blockIdx.x << 6;

    const int lr = tid >> 2;           // 0..63 : tile row
    const int lk = (tid & 3) << 2;     // 0,4,8,12 : k sub-offset

    const int am = bm + lr;
    const int ab = am / L;
    const int ai = am - ab * L;
    const float* ap = A + (size_t)(ab * slotA + ai) * K + lk;
    const float* wp = W + (size_t)(bn + lr) * K + lk;

    const int tm = (tid >> 4) << 2;    // 0..60
    const int tn = (tid & 15) << 2;    // 0..60

    ull acc[4][2];
    #pragma unroll
    for (int i = 0; i < 4; i++) { acc[i][0] = 0ull; acc[i][1] = 0ull; }

    // prefetch + store chunk 0
    float4 av = *reinterpret_cast<const float4*>(ap);
    float4 wv = *reinterpret_cast<const float4*>(wp);
    As[0][lk + 0][lr] = make_float2(av.x, av.x);
    As[0][lk + 1][lr] = make_float2(av.y, av.y);
    As[0][lk + 2][lr] = make_float2(av.z, av.z);
    As[0][lk + 3][lr] = make_float2(av.w, av.w);
    Ws[0][lk + 0][lr] = wv.x; Ws[0][lk + 1][lr] = wv.y;
    Ws[0][lk + 2][lr] = wv.z; Ws[0][lk + 3][lr] = wv.w;
    __syncthreads();

    const int nc = K >> 4;
    for (int c = 0; c < nc; c++) {
        const int buf = c & 1;
        if (c + 1 < nc) {
            av = *reinterpret_cast<const float4*>(ap + ((c + 1) << 4));
            wv = *reinterpret_cast<const float4*>(wp + ((c + 1) << 4));
        }
        #pragma unroll
        for (int k = 0; k < 16; k++) {
            ulonglong2 a01 = *reinterpret_cast<const ulonglong2*>(&As[buf][k][tm]);
            ulonglong2 a23 = *reinterpret_cast<const ulonglong2*>(&As[buf][k][tm + 2]);
            ulonglong2 w01 = *reinterpret_cast<const ulonglong2*>(&Ws[buf][k][tn]);
            fma2(acc[0][0], a01.x, w01.x); fma2(acc[0][1], a01.x, w01.y);
            fma2(acc[1][0], a01.y, w01.x); fma2(acc[1][1], a01.y, w01.y);
            fma2(acc[2][0], a23.x, w01.x); fma2(acc[2][1], a23.x, w01.y);
            fma2(acc[3][0], a23.y, w01.x); fma2(acc[3][1], a23.y, w01.y);
        }
        if (c + 1 < nc) {
            const int nb = buf ^ 1;
            As[nb][lk + 0][lr] = make_float2(av.x, av.x);
            As[nb][lk + 1][lr] = make_float2(av.y, av.y);
            As[nb][lk + 2][lr] = make_float2(av.z, av.z);
            As[nb][lk + 3][lr] = make_float2(av.w, av.w);
            Ws[nb][lk + 0][lr] = wv.x; Ws[nb][lk + 1][lr] = wv.y;
            Ws[nb][lk + 2][lr] = wv.z; Ws[nb][lk + 3][lr] = wv.w;
            __syncthreads();
        }
    }

    float4 bv = *reinterpret_cast<const float4*>(bias + bn + tn);
    #pragma unroll
    for (int i = 0; i < 4; i++) {
        int m = bm + tm + i;
        int b = m / L; int ii = m - b * L;
        float* cp = C + (size_t)(b * slotC + ii) * N + bn + tn;
        union { ull u; float2 f; } u0, u1;
        u0.u = acc[i][0]; u1.u = acc[i][1];
        cp[0] = u0.f.x + bv.x; cp[1] = u0.f.y + bv.y;
        cp[2] = u1.f.x + bv.z; cp[3] = u1.f.y + bv.w;
    }
}

// ---- scatter x_t into slot t of h ----
__global__ void scatter_k(int t)
{
    int idx = blockIdx.x * 256 + threadIdx.x;   // 128*512
    int b = idx >> 9, e = idx & 511;
    g_h[((size_t)b * NSTEP + t) * NE + e] = g_X[((size_t)t * NB + b) * NE + e];
}

// ---- per (batch, head) attention over L<=16 valid positions (no mask) ----
__global__ __launch_bounds__(256) void attn_k(int seqL)
{
    __shared__ float q_s[16][64], k_s[16][64], v_s[16][64];
    __shared__ float p_s[16][17];
    int blk = blockIdx.x; int b = blk >> 3; int hh = blk & 7;
    int tid = threadIdx.x;
    const float* base = g_qkv + (size_t)b * NSTEP * 1536 + hh * 64;
    for (int e = tid; e < 1024; e += 256) {
        int i = e >> 6, d = e & 63;
        if (i < seqL) {
            const float* p = base + (size_t)i * 1536 + d;
            q_s[i][d] = p[0];
            k_s[i][d] = p[512];
            v_s[i][d] = p[1024];
        }
    }
    __syncthreads();
    int si = tid >> 4, sj = tid & 15;
    if (si < seqL && sj < seqL) {
        float s = 0.f;
        #pragma unroll
        for (int d = 0; d < 64; d++) s += q_s[si][d] * k_s[sj][d];
        p_s[si][sj] = s * 0.125f;   // 1/sqrt(64)
    }
    __syncthreads();
    if (tid < seqL) {
        float mx = -1e30f;
        for (int j = 0; j < seqL; j++) mx = fmaxf(mx, p_s[tid][j]);
        float sum = 0.f;
        for (int j = 0; j < seqL; j++) { float e = expf(p_s[tid][j] - mx); p_s[tid][j] = e; sum += e; }
        float inv = 1.f / sum;
        for (int j = 0; j < seqL; j++) p_s[tid][j] *= inv;
    }
    __syncthreads();
    int qi = tid >> 4, d0 = (tid & 15) << 2;
    if (qi < seqL) {
        float o0 = 0, o1 = 0, o2 = 0, o3 = 0;
        for (int j = 0; j < seqL; j++) {
            float p = p_s[qi][j];
            o0 += p * v_s[j][d0];     o1 += p * v_s[j][d0 + 1];
            o2 += p * v_s[j][d0 + 2]; o3 += p * v_s[j][d0 + 3];
        }
        float* op = g_att + ((size_t)b * NSTEP + qi) * NE + hh * 64 + d0;
        op[0] = o0; op[1] = o1; op[2] = o2; op[3] = o3;
    }
}

// ---- h = LN(h + tmp) * scale + bias, rowwise over E=512 ----
__global__ __launch_bounds__(256) void resid_ln_k(
    const float* __restrict__ sc, const float* __restrict__ bi, int seqL)
{
    int r = blockIdx.x;
    int b = r / seqL; int i = r - b * seqL;
    float* hp = g_h + ((size_t)b * NSTEP + i) * NE;
    const float* tp = g_tmp + ((size_t)b * NSTEP + i) * NE;
    int tid = threadIdx.x;
    float y0 = hp[tid] + tp[tid];
    float y1 = hp[tid + 256] + tp[tid + 256];
    float s = y0 + y1, ss = y0 * y0 + y1 * y1;
    __shared__ float shs[8], shq[8];
    __shared__ float mu_sh, inv_sh;
    int lane = tid & 31, w = tid >> 5;
    #pragma unroll
    for (int o = 16; o > 0; o >>= 1) {
        s  += __shfl_down_sync(0xffffffffu, s, o);
        ss += __shfl_down_sync(0xffffffffu, ss, o);
    }
    if (lane == 0) { shs[w] = s; shq[w] = ss; }
    __syncthreads();
    if (tid == 0) {
        float ts = 0, tq = 0;
        #pragma unroll
        for (int k = 0; k < 8; k++) { ts += shs[k]; tq += shq[k]; }
        float mu = ts * (1.f / 512.f);
        float var = tq * (1.f / 512.f) - mu * mu;
        mu_sh = mu; inv_sh = rsqrtf(var + 1e-5f);
    }
    __syncthreads();
    float mu = mu_sh, inv = inv_sh;
    hp[tid]       = (y0 - mu) * inv * sc[tid]       + bi[tid];
    hp[tid + 256] = (y1 - mu) * inv * sc[tid + 256] + bi[tid + 256];
}

// ---- out[t,b,:] = h[b, t] @ Wout^T + b_out ----
__global__ __launch_bounds__(128) void outproj_k(
    const float* __restrict__ Wout, const float* __restrict__ b_out,
    float* __restrict__ out, int t)
{
    int b = blockIdx.x, n = threadIdx.x;
    const float4* hr = reinterpret_cast<const float4*>(g_h + ((size_t)b * NSTEP + t) * NE);
    const float4* wr = reinterpret_cast<const float4*>(Wout + (size_t)n * NE);
    float acc = 0.f;
    #pragma unroll 8
    for (int e = 0; e < 128; e++) {
        float4 a = hr[e], w = wr[e];
        acc += a.x * w.x + a.y * w.y + a.z * w.z + a.w * w.w;
    }
    out[((size_t)t * NB + b) * NOUT + n] = acc + b_out[n];
}

// ---- write new_h: [h_fin | pad passthrough | cur_idx+16] ----
__global__ void assemble_k(const float* __restrict__ hstate, float* __restrict__ outh)
{
    int idx = blockIdx.x * 256 + threadIdx.x;
    if (idx >= NB * NMEM) return;
    int b = idx / NMEM; int j = idx - b * NMEM;
    float v;
    if (j < NSTEP * NE)      v = g_h[(size_t)b * NSTEP * NE + j];   // contiguous first 16 rows
    else if (j < NMEM - 1)   v = hstate[idx];                        // untouched pad region
    else                     v = (float)((int)hstate[idx] + NSTEP);  // cur_idx + 16
    outh[idx] = v;
}

extern "C" void kernel_launch(void* const* d_in, const int* in_sizes, int n_in,
                              void* d_out, int out_size)
{
    const float* seq   = (const float*)d_in[0];
    const float* hst   = (const float*)d_in[1];
    const float* Win   = (const float*)d_in[2];
    const float* b_in  = (const float*)d_in[3];
    const float* Wout  = (const float*)d_in[4];
    const float* b_out = (const float*)d_in[5];
    const float* ipw   = (const float*)d_in[6];
    const float* ipb   = (const float*)d_in[7];
    const float* aow   = (const float*)d_in[8];
    const float* aob   = (const float*)d_in[9];
    const float* l1s   = (const float*)d_in[10];
    const float* l1b   = (const float*)d_in[11];
    const float* l2s   = (const float*)d_in[12];
    const float* l2b   = (const float*)d_in[13];
    const float* ffw   = (const float*)d_in[14];
    const float* ffb   = (const float*)d_in[15];
    float* out = (float*)d_out;

    float *pX, *ph, *pqkv, *patt, *ptmp;
    cudaGetSymbolAddress((void**)&pX,   g_X);
    cudaGetSymbolAddress((void**)&ph,   g_h);
    cudaGetSymbolAddress((void**)&pqkv, g_qkv);
    cudaGetSymbolAddress((void**)&patt, g_att);
    cudaGetSymbolAddress((void**)&ptmp, g_tmp);

    // X = sequences @ Win^T + b_in  (contiguous rows: L = M)
    gemm_bias_k<<<dim3(NE / 64, (NSTEP * NB) / 64), 256>>>(
        seq, Win, b_in, pX, NSTEP * NB, NE, NIN, NSTEP * NB, 0, 0);

    for (int t = 0; t < NSTEP; t++) {
        int Lq = t + 1;
        int M = NB * Lq;
        int mt = M / 64;

        scatter_k<<<(NB * NE) / 256, 256>>>(t);

        for (int l = 0; l < NLAY; l++) {
            gemm_bias_k<<<dim3(3 * NE / 64, mt), 256>>>(
                ph, ipw + (size_t)l * 3 * NE * NE, ipb + l * 3 * NE, pqkv,
                M, 3 * NE, NE, Lq, NSTEP, NSTEP);
            attn_k<<<NB * NH, 256>>>(Lq);
            gemm_bias_k<<<dim3(NE / 64, mt), 256>>>(
                patt, aow + (size_t)l * NE * NE, aob + l * NE, ptmp,
                M, NE, NE, Lq, NSTEP, NSTEP);
            resid_ln_k<<<M, 256>>>(l1s + l * NE, l1b + l * NE, Lq);
            gemm_bias_k<<<dim3(NE / 64, mt), 256>>>(
                ph, ffw + (size_t)l * NE * NE, ffb + l * NE, ptmp,
                M, NE, NE, Lq, NSTEP, NSTEP);
            resid_ln_k<<<M, 256>>>(l2s + l * NE, l2b + l * NE, Lq);
        }
        outproj_k<<<NB, 128>>>(Wout, b_out, out, t);
    }

    assemble_k<<<(NB * NMEM + 255) / 256, 256>>>(hst, out + NSTEP * NB * NOUT);
}

// round 5
// speedup vs baseline: 1.9250x; 1.9250x over previous
// R5: mma.sync (HMMA) bf16 split-precision GEMM — tcgen05 unavailable (.target sm_103)
#include <cuda_runtime.h>
#include <cuda_bf16.h>
#include <cstdint>

#define NSTEP 16
#define NB 128
#define NE 512
#define NH 8
#define NIN 256
#define NOUT 128
#define NMEM 32769
#define NLAY 2

// weight bf16 buffer offsets (elements)
#define OFF_WIN 0
#define OFF_IPW 131072
#define OFF_AOW 1703936
#define OFF_FFW 2228224
#define WTOT    2752512

// ---- scratch ----
__device__ float g_X  [NSTEP * NB * NE];
__device__ float g_h  [NB * NSTEP * NE];
__device__ float g_qkv[NB * NSTEP * 3 * NE];
__device__ float g_tmp[NB * NSTEP * NE];
__device__ __align__(16) __nv_bfloat16 g_hh[NB * NSTEP * NE];
__device__ __align__(16) __nv_bfloat16 g_hl[NB * NSTEP * NE];
__device__ __align__(16) __nv_bfloat16 g_ah[NB * NSTEP * NE];
__device__ __align__(16) __nv_bfloat16 g_al[NB * NSTEP * NE];
__device__ __align__(16) __nv_bfloat16 g_sh[NSTEP * NB * NIN];
__device__ __align__(16) __nv_bfloat16 g_sl[NSTEP * NB * NIN];
__device__ __align__(16) __nv_bfloat16 g_wh[WTOT];
__device__ __align__(16) __nv_bfloat16 g_wl[WTOT];

__device__ __forceinline__ uint32_t smem_u32(const void* p) {
    uint32_t a;
    asm("{ .reg .u64 t; cvta.to.shared.u64 t, %1; cvt.u32.u64 %0, t; }" : "=r"(a) : "l"(p));
    return a;
}

#define LDM4(r, addr) \
    asm volatile("ldmatrix.sync.aligned.m8n8.x4.shared.b16 {%0,%1,%2,%3}, [%4];" \
        : "=r"((r)[0]), "=r"((r)[1]), "=r"((r)[2]), "=r"((r)[3]) : "r"(addr))

#define MMA(d, a, b) \
    asm volatile("mma.sync.aligned.m16n8k16.row.col.f32.bf16.bf16.f32 " \
        "{%0,%1,%2,%3}, {%4,%5,%6,%7}, {%8,%9}, {%0,%1,%2,%3};" \
        : "+f"((d)[0]), "+f"((d)[1]), "+f"((d)[2]), "+f"((d)[3]) \
        : "r"((a)[0]), "r"((a)[1]), "r"((a)[2]), "r"((a)[3]), "r"((b)[0]), "r"((b)[1]))

// ======================= tensor-core GEMM (mma.sync) =======================
// C[m,n] = sum_k (Ah+Al)[m,k]*(Wh+Wl)[n,k] + bias[n]   (3-term split)
// grid = (N/64, M/128), block = 256.  Row m -> (b=m/L, i=m%L).
// M % 128 == 0, N % 64 == 0, K % 32 == 0 always hold here.
__global__ __launch_bounds__(256) void gemm_tc_k(
    const __nv_bfloat16* __restrict__ Ah, const __nv_bfloat16* __restrict__ Al,
    const __nv_bfloat16* __restrict__ Wh, const __nv_bfloat16* __restrict__ Wl,
    const float* __restrict__ bias, float* __restrict__ C,
    int N, int K, int L, int slotA, int slotC)
{
    __shared__ __align__(16) __nv_bfloat16 Ash[128][40];
    __shared__ __align__(16) __nv_bfloat16 Asl[128][40];
    __shared__ __align__(16) __nv_bfloat16 Wsh[64][40];
    __shared__ __align__(16) __nv_bfloat16 Wsl[64][40];

    const int tid  = threadIdx.x;
    const int warp = tid >> 5;
    const int lane = tid & 31;
    const int bm = blockIdx.y << 7;
    const int bn = blockIdx.x << 6;

    // ---- global load mapping ----
    // A: thread handles row tid>>1, 16 consecutive k at offset (tid&1)*16
    const int arow = tid >> 1;
    const int akb  = (tid & 1) << 4;               // 0 or 16
    const int gmL  = bm + arow;
    const int ab   = gmL / L;
    const int ai   = gmL - ab * L;
    const size_t aoff = (size_t)(ab * slotA + ai) * K + akb;
    // W: thread handles row tid>>2, 8 k at offset (tid&3)*8
    const int wrow = tid >> 2;
    const int wkb  = (tid & 3) << 3;
    const size_t woff = (size_t)(bn + wrow) * K + wkb;

    const int warpM = (warp >> 1) << 5;            // 0,32,64,96
    const int warpN = (warp & 1) << 5;             // 0,32

    // ---- ldmatrix smem addresses (byte addresses in shared space) ----
    // A frag (m16k16, 4 8x8 mats): row = warpM+mt*16+(lane&15), kofs=(lane>>4)*8
    const int aRow = (lane & 15);
    const int aKof = (lane >> 4) << 3;
    uint32_t aAh[2], aAl[2];
    aAh[0] = smem_u32(&Ash[warpM + aRow][aKof]);
    aAh[1] = smem_u32(&Ash[warpM + 16 + aRow][aKof]);
    aAl[0] = smem_u32(&Asl[warpM + aRow][aKof]);
    aAl[1] = smem_u32(&Asl[warpM + 16 + aRow][aKof]);
    // B frag pair (two n8k16 tiles per x4): n = (lane&7)+(lane>>4)*8, kofs=((lane>>3)&1)*8
    const int bRow = (lane & 7) + ((lane >> 4) << 3);
    const int bKof = ((lane >> 3) & 1) << 3;
    uint32_t aWh[2], aWl[2];
    aWh[0] = smem_u32(&Wsh[warpN + bRow][bKof]);
    aWh[1] = smem_u32(&Wsh[warpN + 16 + bRow][bKof]);
    aWl[0] = smem_u32(&Wsl[warpN + bRow][bKof]);
    aWl[1] = smem_u32(&Wsl[warpN + 16 + bRow][bKof]);

    float acc[2][4][4];
    #pragma unroll
    for (int mt = 0; mt < 2; mt++)
        #pragma unroll
        for (int nt = 0; nt < 4; nt++)
            #pragma unroll
            for (int j = 0; j < 4; j++) acc[mt][nt][j] = 0.f;

    const int nc = K >> 5;

    // preload chunk 0
    uint4 pa0 = *(const uint4*)(Ah + aoff);
    uint4 pa1 = *(const uint4*)(Ah + aoff + 8);
    uint4 pb0 = *(const uint4*)(Al + aoff);
    uint4 pb1 = *(const uint4*)(Al + aoff + 8);
    uint4 pw0 = *(const uint4*)(Wh + woff);
    uint4 pw1 = *(const uint4*)(Wl + woff);
    *(uint4*)&Ash[arow][akb]     = pa0;
    *(uint4*)&Ash[arow][akb + 8] = pa1;
    *(uint4*)&Asl[arow][akb]     = pb0;
    *(uint4*)&Asl[arow][akb + 8] = pb1;
    *(uint4*)&Wsh[wrow][wkb]     = pw0;
    *(uint4*)&Wsl[wrow][wkb]     = pw1;
    __syncthreads();

    for (int c = 0; c < nc; c++) {
        if (c + 1 < nc) {
            const int ko = (c + 1) << 5;
            pa0 = *(const uint4*)(Ah + aoff + ko);
            pa1 = *(const uint4*)(Ah + aoff + ko + 8);
            pb0 = *(const uint4*)(Al + aoff + ko);
            pb1 = *(const uint4*)(Al + aoff + ko + 8);
            pw0 = *(const uint4*)(Wh + woff + ko);
            pw1 = *(const uint4*)(Wl + woff + ko);
        }

        #pragma unroll
        for (int ks = 0; ks < 2; ks++) {
            const uint32_t kb = ks * 32;           // 16 bf16 = 32 bytes
            uint32_t ah0[4], ah1[4], al0[4], al1[4];
            LDM4(ah0, aAh[0] + kb); LDM4(ah1, aAh[1] + kb);
            LDM4(al0, aAl[0] + kb); LDM4(al1, aAl[1] + kb);
            uint32_t bh[4][2], bl[4][2];
            {
                uint32_t t[4];
                LDM4(t, aWh[0] + kb);
                bh[0][0] = t[0]; bh[0][1] = t[1]; bh[1][0] = t[2]; bh[1][1] = t[3];
                LDM4(t, aWh[1] + kb);
                bh[2][0] = t[0]; bh[2][1] = t[1]; bh[3][0] = t[2]; bh[3][1] = t[3];
                LDM4(t, aWl[0] + kb);
                bl[0][0] = t[0]; bl[0][1] = t[1]; bl[1][0] = t[2]; bl[1][1] = t[3];
                LDM4(t, aWl[1] + kb);
                bl[2][0] = t[0]; bl[2][1] = t[1]; bl[3][0] = t[2]; bl[3][1] = t[3];
            }
            #pragma unroll
            for (int nt = 0; nt < 4; nt++) {
                MMA(acc[0][nt], ah0, bh[nt]);
                MMA(acc[0][nt], ah0, bl[nt]);
                MMA(acc[0][nt], al0, bh[nt]);
                MMA(acc[1][nt], ah1, bh[nt]);
                MMA(acc[1][nt], ah1, bl[nt]);
                MMA(acc[1][nt], al1, bh[nt]);
            }
        }

        if (c + 1 < nc) {
            __syncthreads();
            *(uint4*)&Ash[arow][akb]     = pa0;
            *(uint4*)&Ash[arow][akb + 8] = pa1;
            *(uint4*)&Asl[arow][akb]     = pb0;
            *(uint4*)&Asl[arow][akb + 8] = pb1;
            *(uint4*)&Wsh[wrow][wkb]     = pw0;
            *(uint4*)&Wsl[wrow][wkb]     = pw1;
            __syncthreads();
        }
    }

    // ---- epilogue: c frag (m16n8): c0,c1 @ (lane>>2, (lane&3)*2); c2,c3 @ row+8
    const int cn = bn + warpN + ((lane & 3) << 1);
    #pragma unroll
    for (int mt = 0; mt < 2; mt++) {
        #pragma unroll
        for (int half = 0; half < 2; half++) {
            const int m = bm + warpM + mt * 16 + (lane >> 2) + half * 8;
            const int b = m / L;
            const int i = m - b * L;
            float* cp = C + (size_t)(b * slotC + i) * N + cn;
            #pragma unroll
            for (int nt = 0; nt < 4; nt++) {
                float2 o;
                o.x = acc[mt][nt][half * 2 + 0] + bias[cn + nt * 8];
                o.y = acc[mt][nt][half * 2 + 1] + bias[cn + nt * 8 + 1];
                *(float2*)(cp + nt * 8) = o;
            }
        }
    }
}

// ======================= fp32 -> bf16 hi/lo =======================
__global__ void conv_k(const float* __restrict__ src, __nv_bfloat16* __restrict__ hi,
                       __nv_bfloat16* __restrict__ lo, int n)
{
    int idx = blockIdx.x * 256 + threadIdx.x;
    if (idx >= n) return;
    float x = src[idx];
    __nv_bfloat16 h = __float2bfloat16(x);
    hi[idx] = h;
    lo[idx] = __float2bfloat16(x - __bfloat162float(h));
}

// ---- scatter x_t into slot t of h (+ bf16 split) ----
__global__ void scatter_k(int t)
{
    int idx = blockIdx.x * 256 + threadIdx.x;   // 128*512
    int b = idx >> 9, e = idx & 511;
    float x = g_X[((size_t)t * NB + b) * NE + e];
    size_t d = ((size_t)b * NSTEP + t) * NE + e;
    g_h[d] = x;
    __nv_bfloat16 h = __float2bfloat16(x);
    g_hh[d] = h;
    g_hl[d] = __float2bfloat16(x - __bfloat162float(h));
}

// ---- per (batch, head) attention; writes att as bf16 hi/lo ----
__global__ __launch_bounds__(256) void attn_k(int seqL)
{
    __shared__ float q_s[16][64], k_s[16][64], v_s[16][64];
    __shared__ float p_s[16][17];
    int blk = blockIdx.x; int b = blk >> 3; int hh = blk & 7;
    int tid = threadIdx.x;
    const float* base = g_qkv + (size_t)b * NSTEP * 1536 + hh * 64;
    for (int e = tid; e < 1024; e += 256) {
        int i = e >> 6, d = e & 63;
        if (i < seqL) {
            const float* p = base + (size_t)i * 1536 + d;
            q_s[i][d] = p[0];
            k_s[i][d] = p[512];
            v_s[i][d] = p[1024];
        }
    }
    __syncthreads();
    int si = tid >> 4, sj = tid & 15;
    if (si < seqL && sj < seqL) {
        float s = 0.f;
        #pragma unroll
        for (int d = 0; d < 64; d++) s += q_s[si][d] * k_s[sj][d];
        p_s[si][sj] = s * 0.125f;
    }
    __syncthreads();
    if (tid < seqL) {
        float mx = -1e30f;
        for (int j = 0; j < seqL; j++) mx = fmaxf(mx, p_s[tid][j]);
        float sum = 0.f;
        for (int j = 0; j < seqL; j++) { float e = expf(p_s[tid][j] - mx); p_s[tid][j] = e; sum += e; }
        float inv = 1.f / sum;
        for (int j = 0; j < seqL; j++) p_s[tid][j] *= inv;
    }
    __syncthreads();
    int qi = tid >> 4, d0 = (tid & 15) << 2;
    if (qi < seqL) {
        float o[4] = {0, 0, 0, 0};
        for (int j = 0; j < seqL; j++) {
            float p = p_s[qi][j];
            o[0] += p * v_s[j][d0];     o[1] += p * v_s[j][d0 + 1];
            o[2] += p * v_s[j][d0 + 2]; o[3] += p * v_s[j][d0 + 3];
        }
        size_t d = ((size_t)b * NSTEP + qi) * NE + hh * 64 + d0;
        #pragma unroll
        for (int k = 0; k < 4; k++) {
            __nv_bfloat16 h = __float2bfloat16(o[k]);
            g_ah[d + k] = h;
            g_al[d + k] = __float2bfloat16(o[k] - __bfloat162float(h));
        }
    }
}

// ---- h = LN(h + tmp)*scale + bias  (+ bf16 split) ----
__global__ __launch_bounds__(256) void resid_ln_k(
    const float* __restrict__ sc, const float* __restrict__ bi, int seqL)
{
    int r = blockIdx.x;
    int b = r / seqL; int i = r - b * seqL;
    size_t rowo = ((size_t)b * NSTEP + i) * NE;
    float* hp = g_h + rowo;
    const float* tp = g_tmp + rowo;
    int tid = threadIdx.x;
    float y0 = hp[tid] + tp[tid];
    float y1 = hp[tid + 256] + tp[tid + 256];
    float s = y0 + y1, ss = y0 * y0 + y1 * y1;
    __shared__ float shs[8], shq[8];
    __shared__ float mu_sh, inv_sh;
    int lane = tid & 31, w = tid >> 5;
    #pragma unroll
    for (int o = 16; o > 0; o >>= 1) {
        s  += __shfl_down_sync(0xffffffffu, s, o);
        ss += __shfl_down_sync(0xffffffffu, ss, o);
    }
    if (lane == 0) { shs[w] = s; shq[w] = ss; }
    __syncthreads();
    if (tid == 0) {
        float ts = 0, tq = 0;
        #pragma unroll
        for (int k = 0; k < 8; k++) { ts += shs[k]; tq += shq[k]; }
        float mu = ts * (1.f / 512.f);
        float var = tq * (1.f / 512.f) - mu * mu;
        mu_sh = mu; inv_sh = rsqrtf(var + 1e-5f);
    }
    __syncthreads();
    float mu = mu_sh, inv = inv_sh;
    float v0 = (y0 - mu) * inv * sc[tid]       + bi[tid];
    float v1 = (y1 - mu) * inv * sc[tid + 256] + bi[tid + 256];
    hp[tid] = v0; hp[tid + 256] = v1;
    __nv_bfloat16 h0 = __float2bfloat16(v0);
    __nv_bfloat16 h1 = __float2bfloat16(v1);
    g_hh[rowo + tid] = h0;       g_hl[rowo + tid]       = __float2bfloat16(v0 - __bfloat162float(h0));
    g_hh[rowo + tid + 256] = h1; g_hl[rowo + tid + 256] = __float2bfloat16(v1 - __bfloat162float(h1));
}

// ---- out[t,b,:] = h[b,t] @ Wout^T + b_out ----
__global__ __launch_bounds__(128) void outproj_k(
    const float* __restrict__ Wout, const float* __restrict__ b_out,
    float* __restrict__ out, int t)
{
    int b = blockIdx.x, n = threadIdx.x;
    const float4* hr = reinterpret_cast<const float4*>(g_h + ((size_t)b * NSTEP + t) * NE);
    const float4* wr = reinterpret_cast<const float4*>(Wout + (size_t)n * NE);
    float acc = 0.f;
    #pragma unroll 8
    for (int e = 0; e < 128; e++) {
        float4 a = hr[e], w = wr[e];
        acc += a.x * w.x + a.y * w.y + a.z * w.z + a.w * w.w;
    }
    out[((size_t)t * NB + b) * NOUT + n] = acc + b_out[n];
}

// ---- write new_h ----
__global__ void assemble_k(const float* __restrict__ hstate, float* __restrict__ outh)
{
    int idx = blockIdx.x * 256 + threadIdx.x;
    if (idx >= NB * NMEM) return;
    int b = idx / NMEM; int j = idx - b * NMEM;
    float v;
    if (j < NSTEP * NE)      v = g_h[(size_t)b * NSTEP * NE + j];
    else if (j < NMEM - 1)   v = hstate[idx];
    else                     v = (float)((int)hstate[idx] + NSTEP);
    outh[idx] = v;
}

extern "C" void kernel_launch(void* const* d_in, const int* in_sizes, int n_in,
                              void* d_out, int out_size)
{
    const float* seq   = (const float*)d_in[0];
    const float* hst   = (const float*)d_in[1];
    const float* Win   = (const float*)d_in[2];
    const float* b_in  = (const float*)d_in[3];
    const float* Wout  = (const float*)d_in[4];
    const float* b_out = (const float*)d_in[5];
    const float* ipw   = (const float*)d_in[6];
    const float* ipb   = (const float*)d_in[7];
    const float* aow   = (const float*)d_in[8];
    const float* aob   = (const float*)d_in[9];
    const float* l1s   = (const float*)d_in[10];
    const float* l1b   = (const float*)d_in[11];
    const float* l2s   = (const float*)d_in[12];
    const float* l2b   = (const float*)d_in[13];
    const float* ffw   = (const float*)d_in[14];
    const float* ffb   = (const float*)d_in[15];
    float* out = (float*)d_out;

    float *pX, *pqkv, *ptmp;
    __nv_bfloat16 *phh, *phl, *pah, *pal, *psh, *psl, *pwh, *pwl;
    cudaGetSymbolAddress((void**)&pX,   g_X);
    cudaGetSymbolAddress((void**)&pqkv, g_qkv);
    cudaGetSymbolAddress((void**)&ptmp, g_tmp);
    cudaGetSymbolAddress((void**)&phh,  g_hh);
    cudaGetSymbolAddress((void**)&phl,  g_hl);
    cudaGetSymbolAddress((void**)&pah,  g_ah);
    cudaGetSymbolAddress((void**)&pal,  g_al);
    cudaGetSymbolAddress((void**)&psh,  g_sh);
    cudaGetSymbolAddress((void**)&psl,  g_sl);
    cudaGetSymbolAddress((void**)&pwh,  g_wh);
    cudaGetSymbolAddress((void**)&pwl,  g_wl);

    // convert weights + inputs to bf16 hi/lo
    conv_k<<<(NE * NIN + 255) / 256, 256>>>(Win, pwh + OFF_WIN, pwl + OFF_WIN, NE * NIN);
    conv_k<<<(NLAY * 3 * NE * NE + 255) / 256, 256>>>(ipw, pwh + OFF_IPW, pwl + OFF_IPW, NLAY * 3 * NE * NE);
    conv_k<<<(NLAY * NE * NE + 255) / 256, 256>>>(aow, pwh + OFF_AOW, pwl + OFF_AOW, NLAY * NE * NE);
    conv_k<<<(NLAY * NE * NE + 255) / 256, 256>>>(ffw, pwh + OFF_FFW, pwl + OFF_FFW, NLAY * NE * NE);
    conv_k<<<(NSTEP * NB * NIN + 255) / 256, 256>>>(seq, psh, psl, NSTEP * NB * NIN);

    // X = seq @ Win^T + b_in   (M=2048, N=512, K=256; contiguous rows)
    gemm_tc_k<<<dim3(NE / 64, (NSTEP * NB) / 128), 256>>>(
        psh, psl, pwh + OFF_WIN, pwl + OFF_WIN, b_in, pX,
        NE, NIN, NSTEP * NB, 0, 0);

    for (int t = 0; t < NSTEP; t++) {
        int Lq = t + 1;
        scatter_k<<<(NB * NE) / 256, 256>>>(t);

        for (int l = 0; l < NLAY; l++) {
            gemm_tc_k<<<dim3(3 * NE / 64, Lq), 256>>>(
                phh, phl, pwh + OFF_IPW + (size_t)l * 3 * NE * NE,
                pwl + OFF_IPW + (size_t)l * 3 * NE * NE,
                ipb + l * 3 * NE, pqkv, 3 * NE, NE, Lq, NSTEP, NSTEP);
            attn_k<<<NB * NH, 256>>>(Lq);
            gemm_tc_k<<<dim3(NE / 64, Lq), 256>>>(
                pah, pal, pwh + OFF_AOW + (size_t)l * NE * NE,
                pwl + OFF_AOW + (size_t)l * NE * NE,
                aob + l * NE, ptmp, NE, NE, Lq, NSTEP, NSTEP);
            resid_ln_k<<<NB * Lq, 256>>>(l1s + l * NE, l1b + l * NE, Lq);
            gemm_tc_k<<<dim3(NE / 64, Lq), 256>>>(
                phh, phl, pwh + OFF_FFW + (size_t)l * NE * NE,
                pwl + OFF_FFW + (size_t)l * NE * NE,
                ffb + l * NE, ptmp, NE, NE, Lq, NSTEP, NSTEP);
            resid_ln_k<<<NB * Lq, 256>>>(l2s + l * NE, l2b + l * NE, Lq);
        }
        outproj_k<<<NB, 128>>>(Wout, b_out, out, t);
    }

    assemble_k<<<(NB * NMEM + 255) / 256, 256>>>(hst, out + NSTEP * NB * NOUT);
}